// round 6
// baseline (speedup 1.0000x reference)
#include <cuda_runtime.h>
#include <cuda_fp16.h>
#include <cstdint>

#define N_NODES 8192
#define D_IN    128
#define D_OUT   128

// ---------------- device scratch (static, allocation-free) ----------------
__device__ float  g_dinv[N_NODES];
__device__ __half g_Bh[(size_t)D_OUT * N_NODES];       // B^T: [128][8192] K-major fp16, dinv-scaled
__device__ float  g_part[2][(size_t)N_NODES * D_OUT];  // K-split partial outputs

__device__ __forceinline__ uint32_t smem_u32(const void* p) {
    uint32_t a;
    asm("{ .reg .u64 t; cvta.to.shared.u64 t, %1; cvt.u32.u64 %0, t; }" : "=r"(a) : "l"(p));
    return a;
}
__device__ __forceinline__ void cp_async16(uint32_t dst, const void* src) {
    asm volatile("cp.async.cg.shared.global [%0], [%1], 16;" :: "r"(dst), "l"(src));
}
#define CP_COMMIT() asm volatile("cp.async.commit_group;" ::: "memory")

__device__ __forceinline__ uint32_t pack_h2(float lo, float hi) {
    uint32_t r;
    asm("cvt.rn.f16x2.f32 %0, %1, %2;" : "=r"(r) : "f"(hi), "f"(lo));
    return r;
}
__device__ __forceinline__ void mma_f16_16x8x16(float c[4], uint32_t a0, uint32_t a1, uint32_t a2, uint32_t a3,
                                                uint32_t b0, uint32_t b1) {
    asm volatile(
        "mma.sync.aligned.m16n8k16.row.col.f32.f16.f16.f32 "
        "{%0,%1,%2,%3}, {%4,%5,%6,%7}, {%8,%9}, {%0,%1,%2,%3};"
        : "+f"(c[0]), "+f"(c[1]), "+f"(c[2]), "+f"(c[3])
        : "r"(a0), "r"(a1), "r"(a2), "r"(a3), "r"(b0), "r"(b1));
}
__device__ __forceinline__ void ldsm_x4(uint32_t r[4], uint32_t addr) {
    asm volatile("ldmatrix.sync.aligned.m8n8.x4.shared.b16 {%0,%1,%2,%3}, [%4];"
        : "=r"(r[0]), "=r"(r[1]), "=r"(r[2]), "=r"(r[3]) : "r"(addr));
}

// ================= kernel 1: row sums -> dinv (read-only) =================
__global__ void rowsum_kernel(const float* __restrict__ A) {
    int row = blockIdx.x;
    const float4* arow = reinterpret_cast<const float4*>(A + (size_t)row * N_NODES);
    float4 v[8];
    #pragma unroll
    for (int i = 0; i < 8; ++i) v[i] = __ldcs(&arow[threadIdx.x + i * 256]);
    float s = 0.f;
    #pragma unroll
    for (int i = 0; i < 8; ++i) s += (v[i].x + v[i].y) + (v[i].z + v[i].w);
    #pragma unroll
    for (int o = 16; o; o >>= 1) s += __shfl_xor_sync(0xffffffffu, s, o);
    __shared__ float ws[8];
    if ((threadIdx.x & 31) == 0) ws[threadIdx.x >> 5] = s;
    __syncthreads();
    if (threadIdx.x < 8) {
        float t = ws[threadIdx.x];
        #pragma unroll
        for (int o = 4; o; o >>= 1) t += __shfl_xor_sync(0xffu, t, o);
        if (threadIdx.x == 0) g_dinv[row] = 1.0f / (sqrtf(t) + 1e-8f);
    }
}

// ============ kernel 2: B^T[o][j] = fp16( dinv[j] * (V@W + b)[j][o] ) ============
__global__ void fc_kernel(const float* __restrict__ values, const float* __restrict__ W,
                          const float* __restrict__ bvec) {
    int tid = threadIdx.x;
    int o = tid & 127;
    int half_idx = tid >> 7;
    int j0 = blockIdx.x * 32 + half_idx * 16;
    float acc[16];
    #pragma unroll
    for (int i = 0; i < 16; ++i) acc[i] = 0.f;
    const float* vbase = values + (size_t)j0 * D_IN;
    for (int k = 0; k < D_IN; k += 4) {
        float w0 = W[(k + 0) * D_OUT + o];
        float w1 = W[(k + 1) * D_OUT + o];
        float w2 = W[(k + 2) * D_OUT + o];
        float w3 = W[(k + 3) * D_OUT + o];
        #pragma unroll
        for (int jj = 0; jj < 16; ++jj) {
            float4 v = *reinterpret_cast<const float4*>(vbase + jj * D_IN + k);
            acc[jj] = fmaf(v.x, w0, fmaf(v.y, w1, fmaf(v.z, w2, fmaf(v.w, w3, acc[jj]))));
        }
    }
    float bo = bvec[o];
    uint32_t packed[8];
    #pragma unroll
    for (int p = 0; p < 8; ++p) {
        float y0 = (acc[2 * p]     + bo) * g_dinv[j0 + 2 * p];
        float y1 = (acc[2 * p + 1] + bo) * g_dinv[j0 + 2 * p + 1];
        packed[p] = pack_h2(y0, y1);
    }
    uint4* dst = reinterpret_cast<uint4*>(g_Bh + (size_t)o * N_NODES + j0);
    dst[0] = make_uint4(packed[0], packed[1], packed[2], packed[3]);
    dst[1] = make_uint4(packed[4], packed[5], packed[6], packed[7]);
}

// ================= kernel 3: partial = A[rows, khalf] @ B[khalf, :] (fp16 MMA) =================
// CTA 128x128, BK=32, 8 warps 2m x 2n x 2k. A: fp32 LDG -> cvt -> STS fp16 (2-iter pipeline).
// B: cp.async fp16. k-half accumulators merged through smem at epilogue.
#define BM 128
#define BK 32
#define STAGES 3
#define PITCH 80                      // 64B data + 16B pad per tile row
#define TILE_BYTES (128 * PITCH)      // 10240 per operand
#define STAGE_BYTES (2 * TILE_BYTES)  // 20480
#define GEMM_SMEM 65536               // 3 stages (61440) + epilogue merge reuse (64KB)
#define KSPLIT 2
#define KPER (N_NODES / KSPLIT)       // 4096
#define ITERS (KPER / BK)             // 128

__device__ __forceinline__ void load_B(int it, int buf, int tid, size_t k0, uint32_t smem_base) {
    const size_t kk = k0 + (size_t)it * BK;
    const uint32_t sbase = smem_base + (uint32_t)buf * STAGE_BYTES + TILE_BYTES;
    #pragma unroll
    for (int i = 0; i < 2; ++i) {
        int c = tid + i * 256;            // 0..511 16B chunks
        int row = c >> 2;
        int h = c & 3;
        cp_async16(sbase + (uint32_t)(row * PITCH + h * 16),
                   g_Bh + (size_t)row * N_NODES + kk + (size_t)h * 8);
    }
}

__device__ __forceinline__ void ldg_A(float4 r[4], int it, int tid, int row_base, size_t k0,
                                      const float* __restrict__ A) {
    const int row = row_base + (tid >> 1);
    const size_t kk = k0 + (size_t)it * BK + (size_t)(tid & 1) * 16;
    const float4* src = reinterpret_cast<const float4*>(A + (size_t)row * N_NODES + kk);
    #pragma unroll
    for (int i = 0; i < 4; ++i) r[i] = __ldcs(&src[i]);
}

__device__ __forceinline__ void sts_A(const float4 r[4], int buf, int tid, uint32_t smem_base) {
    const uint32_t base = smem_base + (uint32_t)buf * STAGE_BYTES
                        + (uint32_t)((tid >> 1) * PITCH + (tid & 1) * 32);
    uint32_t u[8];
    #pragma unroll
    for (int i = 0; i < 4; ++i) {
        u[2 * i]     = pack_h2(r[i].x, r[i].y);
        u[2 * i + 1] = pack_h2(r[i].z, r[i].w);
    }
    asm volatile("st.shared.v4.b32 [%0], {%1,%2,%3,%4};" :: "r"(base),
        "r"(u[0]), "r"(u[1]), "r"(u[2]), "r"(u[3]) : "memory");
    asm volatile("st.shared.v4.b32 [%0], {%1,%2,%3,%4};" :: "r"(base + 16),
        "r"(u[4]), "r"(u[5]), "r"(u[6]), "r"(u[7]) : "memory");
}

__global__ void __launch_bounds__(256, 1)
gemm_kernel(const float* __restrict__ A) {
    extern __shared__ float smem[];
    const uint32_t smem_base = smem_u32(smem);
    const int tid = threadIdx.x;
    const int lane = tid & 31;
    const int wid = tid >> 5;
    const int wm = wid & 1;               // 2 warps in m (64 rows)
    const int wn = (wid >> 1) & 1;        // 2 warps in n (64 cols)
    const int kh = wid >> 2;              // 2 warps in k (k16 halves of BK=32)
    const int g  = lane >> 2;
    const int tg = lane & 3;
    const int row_base = blockIdx.x * BM;
    const int ksplit = blockIdx.y;
    const size_t k0 = (size_t)ksplit * KPER;

    const int aOff = (wm * 64 + ((lane >> 3) & 1) * 8 + (lane & 7)) * PITCH
                   + (lane >> 4) * 16 + kh * 32;
    const int bOff = (wn * 64 + ((lane >> 4) & 1) * 8 + (lane & 7)) * PITCH
                   + ((lane >> 3) & 1) * 16 + kh * 32;

    float c[4][8][4];
    #pragma unroll
    for (int mi = 0; mi < 4; ++mi)
        #pragma unroll
        for (int ni = 0; ni < 8; ++ni)
            #pragma unroll
            for (int q = 0; q < 4; ++q) c[mi][ni][q] = 0.f;

    float4 rA[4];

    // prologue: A s0 -> regs -> smem0 ; A s1 -> regs ; B s0, s1 via cp.async
    ldg_A(rA, 0, tid, row_base, k0, A);
    load_B(0, 0, tid, k0, smem_base);
    CP_COMMIT();
    sts_A(rA, 0, tid, smem_base);
    ldg_A(rA, 1, tid, row_base, k0, A);
    load_B(1, 1, tid, k0, smem_base);
    CP_COMMIT();

    for (int it = 0; it < ITERS; ++it) {
        asm volatile("cp.async.wait_group %0;" :: "n"(1) : "memory");
        __syncthreads();

        // stage it+1: regs -> smem ; stage it+2: issue loads
        if (it + 1 < ITERS) sts_A(rA, (it + 1) % STAGES, tid, smem_base);
        if (it + 2 < ITERS) {
            ldg_A(rA, it + 2, tid, row_base, k0, A);
            load_B(it + 2, (it + 2) % STAGES, tid, k0, smem_base);
        }
        CP_COMMIT();

        const uint32_t smA = smem_base + (uint32_t)(it % STAGES) * STAGE_BYTES;
        const uint32_t smB = smA + TILE_BYTES;

        uint32_t a[4][4], b[4][4];
        #pragma unroll
        for (int mi = 0; mi < 4; ++mi)
            ldsm_x4(a[mi], smA + (uint32_t)(aOff + mi * 16 * PITCH));
        #pragma unroll
        for (int cb = 0; cb < 4; ++cb)
            ldsm_x4(b[cb], smB + (uint32_t)(bOff + cb * 16 * PITCH));
        #pragma unroll
        for (int mi = 0; mi < 4; ++mi) {
            #pragma unroll
            for (int ni = 0; ni < 8; ++ni) {
                mma_f16_16x8x16(c[mi][ni], a[mi][0], a[mi][1], a[mi][2], a[mi][3],
                                b[ni >> 1][(ni & 1) * 2], b[ni >> 1][(ni & 1) * 2 + 1]);
            }
        }
    }

    // ---- epilogue: merge k-half partials through smem, then store ----
    __syncthreads();   // stage buffers are dead; reuse full 64KB for merge
    const uint32_t pairBase = smem_base + (uint32_t)(wid & 3) * 16384u;
    if (kh == 1) {
        #pragma unroll
        for (int mi = 0; mi < 4; ++mi)
            #pragma unroll
            for (int ni = 0; ni < 8; ++ni) {
                uint32_t off = pairBase + (uint32_t)(((mi * 8 + ni) * 32 + lane) * 16);
                asm volatile("st.shared.v4.b32 [%0], {%1,%2,%3,%4};" :: "r"(off),
                    "r"(__float_as_uint(c[mi][ni][0])), "r"(__float_as_uint(c[mi][ni][1])),
                    "r"(__float_as_uint(c[mi][ni][2])), "r"(__float_as_uint(c[mi][ni][3])) : "memory");
            }
    }
    __syncthreads();
    if (kh == 0) {
        float* P = g_part[ksplit];
        #pragma unroll
        for (int mi = 0; mi < 4; ++mi) {
            const int r0 = row_base + wm * 64 + mi * 16 + g;
            #pragma unroll
            for (int ni = 0; ni < 8; ++ni) {
                uint32_t off = pairBase + (uint32_t)(((mi * 8 + ni) * 32 + lane) * 16);
                float4 p;
                asm volatile("ld.shared.v4.f32 {%0,%1,%2,%3}, [%4];"
                    : "=f"(p.x), "=f"(p.y), "=f"(p.z), "=f"(p.w) : "r"(off));
                const int col = wn * 64 + ni * 8 + 2 * tg;
                float2 lo = make_float2(c[mi][ni][0] + p.x, c[mi][ni][1] + p.y);
                float2 hi = make_float2(c[mi][ni][2] + p.z, c[mi][ni][3] + p.w);
                *reinterpret_cast<float2*>(P + (size_t)r0 * D_OUT + col) = lo;
                *reinterpret_cast<float2*>(P + (size_t)(r0 + 8) * D_OUT + col) = hi;
            }
        }
    }
}

// ================= kernel 4: out = dinv[row] * (part0 + part1) =================
__global__ void reduce_kernel(float* __restrict__ out) {
    int i = blockIdx.x * 256 + threadIdx.x;
    const float4 p0 = reinterpret_cast<const float4*>(g_part[0])[i];
    const float4 p1 = reinterpret_cast<const float4*>(g_part[1])[i];
    int row = (i * 4) >> 7;
    float s = g_dinv[row];
    float4 r;
    r.x = s * (p0.x + p1.x);
    r.y = s * (p0.y + p1.y);
    r.z = s * (p0.z + p1.z);
    r.w = s * (p0.w + p1.w);
    reinterpret_cast<float4*>(out)[i] = r;
}

// ================= launch =================
extern "C" void kernel_launch(void* const* d_in, const int* in_sizes, int n_in,
                              void* d_out, int out_size) {
    const float* values = (const float*)d_in[0];
    const float* A      = (const float*)d_in[1];
    const float* W      = (const float*)d_in[2];
    const float* b      = (const float*)d_in[3];
    float* out = (float*)d_out;

    rowsum_kernel<<<N_NODES, 256>>>(A);
    fc_kernel<<<N_NODES / 32, 256>>>(values, W, b);
    cudaFuncSetAttribute(gemm_kernel, cudaFuncAttributeMaxDynamicSharedMemorySize, GEMM_SMEM);
    gemm_kernel<<<dim3(N_NODES / BM, KSPLIT), 256, GEMM_SMEM>>>(A);
    reduce_kernel<<<(N_NODES * D_OUT / 4) / 256, 256>>>(out);
}

// round 7
// speedup vs baseline: 1.1511x; 1.1511x over previous
#include <cuda_runtime.h>
#include <cuda_fp16.h>
#include <cstdint>

#define N_NODES 8192
#define D_IN    128
#define D_OUT   128

// ---------------- device scratch (static, allocation-free) ----------------
__device__ float  g_dinv[N_NODES];
__device__ __half g_Ah[(size_t)N_NODES * N_NODES];     // fp16 copy of A (128 MB)
__device__ __half g_Bh[(size_t)D_OUT * N_NODES];       // B^T: [128][8192] K-major fp16, dinv-scaled
__device__ float  g_part[(size_t)N_NODES * D_OUT];     // accumulated output (pre row-scale)

__device__ __forceinline__ uint32_t smem_u32(const void* p) {
    uint32_t a;
    asm("{ .reg .u64 t; cvta.to.shared.u64 t, %1; cvt.u32.u64 %0, t; }" : "=r"(a) : "l"(p));
    return a;
}
__device__ __forceinline__ void cp_async16(uint32_t dst, const void* src) {
    asm volatile("cp.async.cg.shared.global [%0], [%1], 16;" :: "r"(dst), "l"(src));
}
#define CP_COMMIT() asm volatile("cp.async.commit_group;" ::: "memory")

__device__ __forceinline__ uint32_t pack_h2(float lo, float hi) {
    uint32_t r;
    asm("cvt.rn.f16x2.f32 %0, %1, %2;" : "=r"(r) : "f"(hi), "f"(lo));
    return r;
}
__device__ __forceinline__ void mma_f16_16x8x16(float c[4], uint32_t a0, uint32_t a1, uint32_t a2, uint32_t a3,
                                                uint32_t b0, uint32_t b1) {
    asm volatile(
        "mma.sync.aligned.m16n8k16.row.col.f32.f16.f16.f32 "
        "{%0,%1,%2,%3}, {%4,%5,%6,%7}, {%8,%9}, {%0,%1,%2,%3};"
        : "+f"(c[0]), "+f"(c[1]), "+f"(c[2]), "+f"(c[3])
        : "r"(a0), "r"(a1), "r"(a2), "r"(a3), "r"(b0), "r"(b1));
}
__device__ __forceinline__ void ldsm_x4(uint32_t r[4], uint32_t addr) {
    asm volatile("ldmatrix.sync.aligned.m8n8.x4.shared.b16 {%0,%1,%2,%3}, [%4];"
        : "=r"(r[0]), "=r"(r[1]), "=r"(r[2]), "=r"(r[3]) : "r"(addr));
}

// ================= kernel 1: row sums -> dinv, plus A -> fp16 =================
__global__ void rowsum_convert_kernel(const float* __restrict__ A) {
    int row = blockIdx.x;
    const float4* arow = reinterpret_cast<const float4*>(A + (size_t)row * N_NODES);
    uint4* dst = reinterpret_cast<uint4*>(g_Ah + (size_t)row * N_NODES);
    float s = 0.f;
    #pragma unroll
    for (int i = 0; i < 4; ++i) {
        int c = threadIdx.x + i * 256;
        float4 a = __ldcs(&arow[2 * c]);
        float4 b = __ldcs(&arow[2 * c + 1]);
        s += ((a.x + a.y) + (a.z + a.w)) + ((b.x + b.y) + (b.z + b.w));
        uint4 u;
        u.x = pack_h2(a.x, a.y);
        u.y = pack_h2(a.z, a.w);
        u.z = pack_h2(b.x, b.y);
        u.w = pack_h2(b.z, b.w);
        dst[c] = u;
    }
    #pragma unroll
    for (int o = 16; o; o >>= 1) s += __shfl_xor_sync(0xffffffffu, s, o);
    __shared__ float ws[8];
    if ((threadIdx.x & 31) == 0) ws[threadIdx.x >> 5] = s;
    __syncthreads();
    if (threadIdx.x < 8) {
        float t = ws[threadIdx.x];
        #pragma unroll
        for (int o = 4; o; o >>= 1) t += __shfl_xor_sync(0xffu, t, o);
        if (threadIdx.x == 0) g_dinv[row] = 1.0f / (sqrtf(t) + 1e-8f);
    }
}

// ============ kernel 2: B^T[o][j] = fp16( dinv[j] * (V@W + b)[j][o] ) ============
__global__ void fc_kernel(const float* __restrict__ values, const float* __restrict__ W,
                          const float* __restrict__ bvec) {
    int tid = threadIdx.x;
    int o = tid & 127;
    int half_idx = tid >> 7;
    int j0 = blockIdx.x * 32 + half_idx * 16;
    float acc[16];
    #pragma unroll
    for (int i = 0; i < 16; ++i) acc[i] = 0.f;
    const float* vbase = values + (size_t)j0 * D_IN;
    for (int k = 0; k < D_IN; k += 4) {
        float w0 = W[(k + 0) * D_OUT + o];
        float w1 = W[(k + 1) * D_OUT + o];
        float w2 = W[(k + 2) * D_OUT + o];
        float w3 = W[(k + 3) * D_OUT + o];
        #pragma unroll
        for (int jj = 0; jj < 16; ++jj) {
            float4 v = *reinterpret_cast<const float4*>(vbase + jj * D_IN + k);
            acc[jj] = fmaf(v.x, w0, fmaf(v.y, w1, fmaf(v.z, w2, fmaf(v.w, w3, acc[jj]))));
        }
    }
    float bo = bvec[o];
    uint32_t packed[8];
    #pragma unroll
    for (int p = 0; p < 8; ++p) {
        float y0 = (acc[2 * p]     + bo) * g_dinv[j0 + 2 * p];
        float y1 = (acc[2 * p + 1] + bo) * g_dinv[j0 + 2 * p + 1];
        packed[p] = pack_h2(y0, y1);
    }
    uint4* dst = reinterpret_cast<uint4*>(g_Bh + (size_t)o * N_NODES + j0);
    dst[0] = make_uint4(packed[0], packed[1], packed[2], packed[3]);
    dst[1] = make_uint4(packed[4], packed[5], packed[6], packed[7]);
}

// ================= kernel 3: balanced persistent GEMM over 148 CTAs =================
// Work unit = (rowblock 128 rows, BK=64 K-chunk). 64 rowblocks x 128 chunks = 8192 units,
// assigned contiguously (rowblock-major) to 148 CTAs (55/56 each, <=1 rowblock boundary).
// Accumulators flushed to g_part via atomicAdd (both k-half warps add independently).
#define BM 128
#define BK 64
#define STAGES 3
#define PITCH 144                     // 128B data + 16B pad per tile row (ldsm conflict-free)
#define TILE_BYTES (128 * PITCH)      // 18432 per operand
#define STAGE_BYTES (2 * TILE_BYTES)  // 36864
#define GEMM_SMEM (STAGES * STAGE_BYTES)   // 110592
#define NCTA 148
#define TOTAL_UNITS 8192              // 64 rowblocks * 128 chunks

__device__ __forceinline__ void load_stage(int u, int buf, int tid, uint32_t smem_base) {
    const int row_base = (u >> 7) * BM;
    const size_t kk = (size_t)(u & 127) * BK;       // in halves
    const uint32_t sbase = smem_base + (uint32_t)buf * STAGE_BYTES;
    #pragma unroll
    for (int i = 0; i < 8; ++i) {
        int c = tid + i * 256;            // 0..2047 16B chunks
        int tile = c >> 10;               // 0: A, 1: B
        int within = c & 1023;
        int row = within >> 3;            // 0..127
        int h = within & 7;               // 16B chunk within 128B row
        uint32_t dst = sbase + (uint32_t)tile * TILE_BYTES + (uint32_t)(row * PITCH + h * 16);
        const __half* src = (tile == 0)
            ? g_Ah + (size_t)(row_base + row) * N_NODES + kk + (size_t)h * 8
            : g_Bh + (size_t)row              * N_NODES + kk + (size_t)h * 8;
        cp_async16(dst, src);
    }
}

__global__ void __launch_bounds__(256, 1)
gemm_kernel() {
    extern __shared__ float smem[];
    const uint32_t smem_base = smem_u32(smem);
    const int tid = threadIdx.x;
    const int lane = tid & 31;
    const int wid = tid >> 5;
    const int wm = wid & 1;               // 2 warps in m (64 rows)
    const int wn = (wid >> 1) & 1;        // 2 warps in n (64 cols)
    const int kh = wid >> 2;              // 2 warps in k
    const int g  = lane >> 2;
    const int tg = lane & 3;

    // contiguous unit range for this CTA: 52 CTAs get 56 units, 96 get 55
    const int cta = blockIdx.x;
    const int start = cta * 55 + min(cta, 52);
    const int count = 55 + (cta < 52 ? 1 : 0);

    // ldmatrix per-lane address components (PITCH-byte rows, 128B data)
    const int aOff = (wm * 64 + ((lane >> 3) & 1) * 8 + (lane & 7)) * PITCH
                   + (lane >> 4) * 16 + kh * 32;
    const int bOff = (wn * 64 + ((lane >> 4) & 1) * 8 + (lane & 7)) * PITCH
                   + ((lane >> 3) & 1) * 16 + kh * 32;

    float c[4][8][4];
    #pragma unroll
    for (int mi = 0; mi < 4; ++mi)
        #pragma unroll
        for (int ni = 0; ni < 8; ++ni)
            #pragma unroll
            for (int q = 0; q < 4; ++q) c[mi][ni][q] = 0.f;

    load_stage(start, 0, tid, smem_base);
    CP_COMMIT();
    load_stage(start + 1, 1, tid, smem_base);    // count >= 55, always valid
    CP_COMMIT();

    for (int j = 0; j < count; ++j) {
        const int u = start + j;

        // rowblock boundary: flush accumulated partial for previous rowblock
        if (j > 0 && (u & 127) == 0) {
            const int prb = (u - 1) >> 7;
            float* P = g_part;
            #pragma unroll
            for (int mi = 0; mi < 4; ++mi) {
                const int r0 = prb * BM + wm * 64 + mi * 16 + g;
                #pragma unroll
                for (int ni = 0; ni < 8; ++ni) {
                    const int col = wn * 64 + ni * 8 + 2 * tg;
                    atomicAdd(P + (size_t)r0 * D_OUT + col,           c[mi][ni][0]);
                    atomicAdd(P + (size_t)r0 * D_OUT + col + 1,       c[mi][ni][1]);
                    atomicAdd(P + (size_t)(r0 + 8) * D_OUT + col,     c[mi][ni][2]);
                    atomicAdd(P + (size_t)(r0 + 8) * D_OUT + col + 1, c[mi][ni][3]);
                    c[mi][ni][0] = c[mi][ni][1] = c[mi][ni][2] = c[mi][ni][3] = 0.f;
                }
            }
        }

        asm volatile("cp.async.wait_group %0;" :: "n"(1) : "memory");
        __syncthreads();

        if (j + 2 < count) load_stage(u + 2, (j + 2) % STAGES, tid, smem_base);
        CP_COMMIT();

        const uint32_t smA = smem_base + (uint32_t)(j % STAGES) * STAGE_BYTES;
        const uint32_t smB = smA + TILE_BYTES;

        #pragma unroll
        for (int ks = 0; ks < 2; ++ks) {
            const uint32_t kb = (uint32_t)(ks * 64);
            uint32_t a[4][4], b[4][4];
            #pragma unroll
            for (int mi = 0; mi < 4; ++mi)
                ldsm_x4(a[mi], smA + (uint32_t)(aOff + mi * 16 * PITCH) + kb);
            #pragma unroll
            for (int cb = 0; cb < 4; ++cb)
                ldsm_x4(b[cb], smB + (uint32_t)(bOff + cb * 16 * PITCH) + kb);
            #pragma unroll
            for (int mi = 0; mi < 4; ++mi) {
                #pragma unroll
                for (int ni = 0; ni < 8; ++ni) {
                    mma_f16_16x8x16(c[mi][ni], a[mi][0], a[mi][1], a[mi][2], a[mi][3],
                                    b[ni >> 1][(ni & 1) * 2], b[ni >> 1][(ni & 1) * 2 + 1]);
                }
            }
        }
    }

    // final flush
    {
        const int prb = (start + count - 1) >> 7;
        float* P = g_part;
        #pragma unroll
        for (int mi = 0; mi < 4; ++mi) {
            const int r0 = prb * BM + wm * 64 + mi * 16 + g;
            #pragma unroll
            for (int ni = 0; ni < 8; ++ni) {
                const int col = wn * 64 + ni * 8 + 2 * tg;
                atomicAdd(P + (size_t)r0 * D_OUT + col,           c[mi][ni][0]);
                atomicAdd(P + (size_t)r0 * D_OUT + col + 1,       c[mi][ni][1]);
                atomicAdd(P + (size_t)(r0 + 8) * D_OUT + col,     c[mi][ni][2]);
                atomicAdd(P + (size_t)(r0 + 8) * D_OUT + col + 1, c[mi][ni][3]);
            }
        }
    }
}

// ================= kernel 4: out = dinv[row] * g_part =================
__global__ void reduce_kernel(float* __restrict__ out) {
    int i = blockIdx.x * 256 + threadIdx.x;
    const float4 p = reinterpret_cast<const float4*>(g_part)[i];
    int row = (i * 4) >> 7;
    float s = g_dinv[row];
    float4 r;
    r.x = s * p.x;
    r.y = s * p.y;
    r.z = s * p.z;
    r.w = s * p.w;
    reinterpret_cast<float4*>(out)[i] = r;
}

// ================= launch =================
extern "C" void kernel_launch(void* const* d_in, const int* in_sizes, int n_in,
                              void* d_out, int out_size) {
    const float* values = (const float*)d_in[0];
    const float* A      = (const float*)d_in[1];
    const float* W      = (const float*)d_in[2];
    const float* b      = (const float*)d_in[3];
    float* out = (float*)d_out;

    void* part_ptr = nullptr;
    cudaGetSymbolAddress(&part_ptr, g_part);
    cudaMemsetAsync(part_ptr, 0, (size_t)N_NODES * D_OUT * sizeof(float));

    rowsum_convert_kernel<<<N_NODES, 256>>>(A);
    fc_kernel<<<N_NODES / 32, 256>>>(values, W, b);
    cudaFuncSetAttribute(gemm_kernel, cudaFuncAttributeMaxDynamicSharedMemorySize, GEMM_SMEM);
    gemm_kernel<<<NCTA, 256, GEMM_SMEM>>>();
    reduce_kernel<<<(N_NODES * D_OUT / 4) / 256, 256>>>(out);
}